// round 11
// baseline (speedup 1.0000x reference)
#include <cuda_runtime.h>
#include <cstdint>

#define N_MAX 100000
#define E_MAX 1600000
#define NBLK_SCAN 128   // max scan blocks (n/1024 <= 98)
#define AGG_NPB 64      // nodes per fused block
#define SS_STRIDE 66    // padded row stride for sS (floats); 264B rows (8B aligned)

// ---------------- scratch (static device memory; no allocation) ----------------
// single zero-init buffer: [deg_out | deg_in | blk_flag]
__device__ int   g_zbuf[2 * N_MAX + NBLK_SCAN];
#define P_DEG_OUT (g_zbuf)
#define P_DEG_IN  (g_zbuf + N_MAX)
#define P_FLAG    (g_zbuf + 2 * N_MAX)
__device__ float g_norm_src[N_MAX];
__device__ float g_norm_dst[N_MAX];
__device__ int   g_row_ptr[N_MAX + 1];
__device__ int   g_fill[N_MAX];
__device__ int   g_col[E_MAX];
__device__ float g_a[N_MAX * 64];   // ping: pre-scaled features (norm_src * h)
__device__ float g_b[N_MAX * 64];   // pong
__device__ unsigned char g_mask[N_MAX * 64];  // 2 layers x pairs, 1 byte per col-pair
__device__ int g_blk_sum[NBLK_SCAN];

// ---------------- threefry-2x32 (exact JAX algorithm, partitionable path) ----------------
__device__ __forceinline__ void d_threefry(uint32_t k0, uint32_t k1,
                                           uint32_t x0, uint32_t x1,
                                           uint32_t& y0, uint32_t& y1) {
    uint32_t k2 = k0 ^ k1 ^ 0x1BD11BDAu;
    x0 += k0; x1 += k1;
#define TFR(r) { x0 += x1; x1 = __funnelshift_l(x1, x1, r); x1 ^= x0; }
    TFR(13) TFR(15) TFR(26) TFR(6)
    x0 += k1; x1 += k2 + 1u;
    TFR(17) TFR(29) TFR(16) TFR(24)
    x0 += k2; x1 += k0 + 2u;
    TFR(13) TFR(15) TFR(26) TFR(6)
    x0 += k0; x1 += k1 + 3u;
    TFR(17) TFR(29) TFR(16) TFR(24)
    x0 += k1; x1 += k2 + 4u;
    TFR(13) TFR(15) TFR(26) TFR(6)
    x0 += k2; x1 += k0 + 5u;
#undef TFR
    y0 = x0; y1 = x1;
}

static inline uint32_t h_rotl(uint32_t x, int r) { return (x << r) | (x >> (32 - r)); }
static void h_threefry(uint32_t k0, uint32_t k1, uint32_t x0, uint32_t x1,
                       uint32_t& y0, uint32_t& y1) {
    uint32_t k2 = k0 ^ k1 ^ 0x1BD11BDAu;
    x0 += k0; x1 += k1;
#define TFR(r) { x0 += x1; x1 = h_rotl(x1, r); x1 ^= x0; }
    TFR(13) TFR(15) TFR(26) TFR(6)
    x0 += k1; x1 += k2 + 1u;
    TFR(17) TFR(29) TFR(16) TFR(24)
    x0 += k2; x1 += k0 + 2u;
    TFR(13) TFR(15) TFR(26) TFR(6)
    x0 += k0; x1 += k1 + 3u;
    TFR(17) TFR(29) TFR(16) TFR(24)
    x0 += k1; x1 += k2 + 4u;
    TFR(13) TFR(15) TFR(26) TFR(6)
    x0 += k2; x1 += k0 + 5u;
#undef TFR
    y0 = x0; y1 = x1;
}

// ---------------- degree count + dropout-mask precompute ----------------
// Edge part is L2-atomic-latency-bound (issue ~5%) — the threefry ALU work
// fills the idle issue slots for free.
// Mask layout: g_mask[layer*pairs + node*32 + c] bit0 = keep col 2c, bit1 = keep 2c+1.
__global__ void k_degree_mask(const int* __restrict__ src, const int* __restrict__ dst,
                              int e, int pairs, int maskWords,
                              uint32_t d0k0, uint32_t d0k1,
                              uint32_t d1k0, uint32_t d1k1) {
    int j = blockIdx.x * blockDim.x + threadIdx.x;
    if (j < e) {
        atomicAdd(&P_DEG_OUT[src[j]], 1);
        atomicAdd(&P_DEG_IN[dst[j]], 1);
    }
    if (j < maskWords) {
        int p0 = 4 * j;                       // first of 4 pair-slots (pairs%4==0)
        int layer = (p0 >= pairs);
        uint32_t k0 = layer ? d1k0 : d0k0;
        uint32_t k1 = layer ? d1k1 : d0k1;
        uint32_t plbase = (uint32_t)(p0 - layer * pairs);
        uint32_t word = 0;
#pragma unroll
        for (int q = 0; q < 4; q++) {
            uint32_t idx = 2u * (plbase + q);  // element index = node*64 + 2c
            uint32_t y0, y1, z0, z1;
            d_threefry(k0, k1, 0u, idx, y0, y1);
            d_threefry(k0, k1, 0u, idx + 1u, z0, z1);
            uint32_t b = (1u ^ ((y0 ^ y1) >> 31)) | ((1u ^ ((z0 ^ z1) >> 31)) << 1);
            word |= b << (8 * q);
        }
        ((uint32_t*)g_mask)[j] = word;
    }
}

// fused: norms + single-pass exclusive scan (decoupled lookback) -> row_ptr / fill
// + U0 = norm_src * x  (smem-shared norms, coalesced float4)
__global__ void k_scan_norm_scale(const float* __restrict__ x, int n, int e) {
    __shared__ int s[1024];
    __shared__ float snorm[1024];
    __shared__ int s_prefix;
    int b = blockIdx.x, t = threadIdx.x, i = b * 1024 + t;
    int din = (i < n) ? P_DEG_IN[i] : 0;
    float ns = 0.f;
    if (i < n) {
        int a = P_DEG_OUT[i];
        ns = (a > 0) ? rsqrtf((float)a) : 0.f;
        g_norm_src[i] = ns;
        g_norm_dst[i] = (din > 0) ? rsqrtf((float)din) : 0.f;
    }
    snorm[t] = ns;
    s[t] = din;
    __syncthreads();
    for (int off = 1; off < 1024; off <<= 1) {
        int a = (t >= off) ? s[t - off] : 0;
        __syncthreads();
        s[t] += a;
        __syncthreads();
    }
    if (t == 0) {
        s_prefix = 0;
        g_blk_sum[b] = s[1023];
        __threadfence();
        *((volatile int*)&P_FLAG[b]) = 1;
    }
    __syncthreads();
    if (t < b) {
        while (*((volatile int*)&P_FLAG[t]) == 0) {}
        int v = *((volatile int*)&g_blk_sum[t]);
        atomicAdd(&s_prefix, v);
    }
    __syncthreads();
    int excl = s[t] - din + s_prefix;
    if (i < n) { g_row_ptr[i] = excl; g_fill[i] = excl; }
    if (i == 0) g_row_ptr[n] = e;

    // fused scale: g_a[node][:] = norm_src[node] * x[node][:]
    const float4* x4 = (const float4*)x;
    int f4base = b * 1024 * 16;
#pragma unroll
    for (int q = 0; q < 16; q++) {
        int idx = f4base + q * 1024 + t;
        if (idx < n * 16) {
            float nv = snorm[(idx >> 4) - b * 1024];
            float4 v = x4[idx];
            v.x *= nv; v.y *= nv; v.z *= nv; v.w *= nv;
            ((float4*)g_a)[idx] = v;
        }
    }
}

__global__ void k_csr(const int* __restrict__ src, const int* __restrict__ dst, int e) {
    int i = blockIdx.x * blockDim.x + threadIdx.x;
    if (i < e) {
        int p = atomicAdd(&g_fill[dst[i]], 1);
        g_col[p] = src[i];
    }
}

// ---------------- packed f32x2 helpers ----------------
__device__ __forceinline__ unsigned long long pk2(float x, float y) {
    unsigned long long r;
    asm("mov.b64 %0, {%1,%2};" : "=l"(r) : "f"(x), "f"(y));
    return r;
}
__device__ __forceinline__ void fma2(unsigned long long& d, unsigned long long a, unsigned long long b) {
    asm("fma.rn.f32x2 %0, %1, %2, %0;" : "+l"(d) : "l"(a), "l"(b));
}
__device__ __forceinline__ void add2(unsigned long long& d, unsigned long long v) {
    asm("add.rn.f32x2 %0, %0, %1;" : "+l"(d) : "l"(v));
}
__device__ __forceinline__ float2 upk2(unsigned long long v) {
    float2 r;
    asm("mov.b64 {%0,%1}, %2;" : "=f"(r.x), "=f"(r.y) : "l"(v));
    return r;
}

// ---------------- fused aggregation + tiled GEMM + epilogue ----------------
// Block = 256 threads, 64 nodes.
//  phase 1: warp w gathers nodes base+8w..base+8w+7 into sS[64][66].
//           int4 col loads + 8-edge unroll; packed f32x2 accumulates
//           (1 FADD2/edge), two alternating accumulators for ILP.
//  phase 2: tiled GEMM on smem S (4 rows x 2 cpairs per thread) vs staged W;
//           precomputed dropout-mask bytes loaded before GEMM (L1-resident).
//  phase 3: epilogue (norm_dst, bias, relu, mask, norm_src prescale)
template <int LAYER>
__global__ void __launch_bounds__(256) k_aggemm(const float* __restrict__ U,
                                                float* __restrict__ Unext,
                                                const float* __restrict__ W,
                                                const float* __restrict__ bias,
                                                int pairs, int n) {
    __shared__ unsigned long long sW[64 * 32]; // [k][cpair] packed (W[k][2c], W[k][2c+1])
    __shared__ float sS[AGG_NPB * SS_STRIDE];  // [local node][k], padded
    int t = threadIdx.x;
    int base = blockIdx.x * AGG_NPB;
    int w = t >> 5, lane = t & 31;
    int rid = t >> 4;       // epilogue row id
    int cid = t & 15;       // epilogue col-pair id

    // stage W (16KB; one-time per 64 nodes)
    const float2* Wv = (const float2*)W;
#pragma unroll
    for (int q = 0; q < 8; q++) {
        int idx = t + q * 256;
        float2 wv = Wv[idx];
        sW[idx] = pk2(wv.x, wv.y);
    }

    // phase 1: gather-sum 8 nodes per warp (lane = col pair)
    const unsigned long long* T2 = (const unsigned long long*)U;
#pragma unroll 1
    for (int r = 0; r < 8; r++) {
        int node = base + w * 8 + r;
        unsigned long long acc0 = 0ull, acc1 = 0ull;
        int s = 0, e = 0;
        if (node < n) { s = g_row_ptr[node]; e = g_row_ptr[node + 1]; }

        int i = s;
        for (; i < e && (i & 3); i++) {            // align to int4
            add2(acc0, T2[g_col[i] * 32 + lane]);
        }
        for (; i + 8 <= e; i += 8) {               // 8 edges / iter
            int4 c0 = *(const int4*)&g_col[i];
            int4 c1 = *(const int4*)&g_col[i + 4];
            unsigned long long v0 = T2[c0.x * 32 + lane];
            unsigned long long v1 = T2[c0.y * 32 + lane];
            unsigned long long v2 = T2[c0.z * 32 + lane];
            unsigned long long v3 = T2[c0.w * 32 + lane];
            unsigned long long v4 = T2[c1.x * 32 + lane];
            unsigned long long v5 = T2[c1.y * 32 + lane];
            unsigned long long v6 = T2[c1.z * 32 + lane];
            unsigned long long v7 = T2[c1.w * 32 + lane];
            add2(acc0, v0); add2(acc1, v1);
            add2(acc0, v2); add2(acc1, v3);
            add2(acc0, v4); add2(acc1, v5);
            add2(acc0, v6); add2(acc1, v7);
        }
        if (i + 4 <= e) {                           // 4 edges
            int4 c0 = *(const int4*)&g_col[i];
            unsigned long long v0 = T2[c0.x * 32 + lane];
            unsigned long long v1 = T2[c0.y * 32 + lane];
            unsigned long long v2 = T2[c0.z * 32 + lane];
            unsigned long long v3 = T2[c0.w * 32 + lane];
            add2(acc0, v0); add2(acc1, v1);
            add2(acc0, v2); add2(acc1, v3);
            i += 4;
        }
        for (; i < e; i++) {                        // tail
            add2(acc0, T2[g_col[i] * 32 + lane]);
        }
        add2(acc0, acc1);
        ((unsigned long long*)&sS[(w * 8 + r) * SS_STRIDE])[lane] = acc0;
    }
    __syncthreads();

    // mask bytes for this thread's 8 (node, cpair) outputs — issue before GEMM
    unsigned char mb[4][2];
    if (LAYER != 2) {
        const unsigned char* mbase = g_mask + LAYER * pairs;
#pragma unroll
        for (int i = 0; i < 4; i++)
#pragma unroll
            for (int j = 0; j < 2; j++)
                mb[i][j] = mbase[(base + rid + 16 * i) * 32 + cid + 16 * j];
    }

    // phase 2: tiled GEMM. thread: rows rid+16i (i=0..3), cpairs cid+16j (j=0..1).
    unsigned long long acc[4][2];
#pragma unroll
    for (int i = 0; i < 4; i++)
#pragma unroll
        for (int j = 0; j < 2; j++) acc[i][j] = 0ull;

#pragma unroll 8
    for (int k = 0; k < 64; k++) {
        unsigned long long a[4], b[2];
#pragma unroll
        for (int i = 0; i < 4; i++) {
            float h = sS[(rid + 16 * i) * SS_STRIDE + k];
            a[i] = pk2(h, h);
        }
#pragma unroll
        for (int j = 0; j < 2; j++) b[j] = sW[k * 32 + cid + 16 * j];
#pragma unroll
        for (int i = 0; i < 4; i++)
#pragma unroll
            for (int j = 0; j < 2; j++) fma2(acc[i][j], a[i], b[j]);
    }

    // phase 3: epilogue
#pragma unroll
    for (int i = 0; i < 4; i++) {
        int node = base + rid + 16 * i;
        if (node < n) {
            float nd = g_norm_dst[node];
            float ns = (LAYER != 2) ? g_norm_src[node] : 0.f;
#pragma unroll
            for (int j = 0; j < 2; j++) {
                int c = cid + 16 * j;
                float2 bb = ((const float2*)bias)[c];
                float2 v = upk2(acc[i][j]);
                float ox = v.x * nd + bb.x;
                float oy = v.y * nd + bb.y;
                if (LAYER != 2) {
                    ox = fmaxf(ox, 0.f);
                    oy = fmaxf(oy, 0.f);
                    ox = (mb[i][j] & 1) ? ox * 2.f * ns : 0.f;
                    oy = (mb[i][j] & 2) ? oy * 2.f * ns : 0.f;
                }
                ((float2*)Unext)[node * 32 + c] = make_float2(ox, oy);
            }
        }
    }
}

// ---------------- launch ----------------
extern "C" void kernel_launch(void* const* d_in, const int* in_sizes, int n_in,
                              void* d_out, int out_size) {
    const float* x  = (const float*)d_in[0];
    const float* W0 = (const float*)d_in[1];
    const float* b0 = (const float*)d_in[2];
    const float* W1 = (const float*)d_in[3];
    const float* b1 = (const float*)d_in[4];
    const float* W2 = (const float*)d_in[5];
    const float* b2 = (const float*)d_in[6];
    const int*   src = (const int*)d_in[7];
    const int*   dst = (const int*)d_in[8];
    int n = in_sizes[0] / 64;
    int e = in_sizes[7];
    float* out = (float*)d_out;

    int nb = (n + 1023) / 1024;   // <= 98: all scan blocks resident, lookback safe
    int pairs = n * 32;           // mask col-pairs per layer (divisible by 4)
    int maskWords = (2 * pairs) / 4;

    uint32_t d0k0, d0k1, d1k0, d1k1;
    h_threefry(0u, 1u, 0u, 0u, d0k0, d0k1);
    h_threefry(0u, 1u, 0u, 1u, d1k0, d1k1);

    float* gA; cudaGetSymbolAddress((void**)&gA, g_a);
    float* gB; cudaGetSymbolAddress((void**)&gB, g_b);
    void* pZ; cudaGetSymbolAddress(&pZ, g_zbuf);

    int aB = (n + AGG_NPB - 1) / AGG_NPB;
    int dThreads = (e > maskWords) ? e : maskWords;

    cudaMemsetAsync(pZ, 0, (size_t)(2 * N_MAX + NBLK_SCAN) * sizeof(int));

    k_degree_mask<<<(dThreads + 255) / 256, 256>>>(src, dst, e, pairs, maskWords,
                                                   d0k0, d0k1, d1k0, d1k1);     // 0
    k_scan_norm_scale<<<nb, 1024>>>(x, n, e);                                   // 1
    k_csr<<<(e + 255) / 256, 256>>>(src, dst, e);                               // 2
    k_aggemm<0><<<aB, 256>>>(gA, gB, W0, b0, pairs, n);                         // 3 (profiled)
    k_aggemm<1><<<aB, 256>>>(gB, gA, W1, b1, pairs, n);                         // 4
    k_aggemm<2><<<aB, 256>>>(gA, out, W2, b2, pairs, n);                        // 5
}

// round 12
// speedup vs baseline: 1.0454x; 1.0454x over previous
#include <cuda_runtime.h>
#include <cstdint>

#define N_MAX 100000
#define E_MAX 1600000
#define NBLK_SCAN 128   // max scan blocks (n/1024 <= 98)
#define AGG_NPB 64      // nodes per fused block
#define SS_STRIDE 66    // padded row stride for sS (floats); rows 264B (8B aligned)

// ---------------- scratch (static device memory; no allocation) ----------------
// single zero-init buffer: [deg_out | deg_in | blk_flag]
__device__ int   g_zbuf[2 * N_MAX + NBLK_SCAN];
#define P_DEG_OUT (g_zbuf)
#define P_DEG_IN  (g_zbuf + N_MAX)
#define P_FLAG    (g_zbuf + 2 * N_MAX)
__device__ float g_norm_src[N_MAX];
__device__ float g_norm_dst[N_MAX];
__device__ int   g_row_ptr[N_MAX + 1];
__device__ int   g_fill[N_MAX];
__device__ int   g_col[E_MAX];
__device__ float g_a[N_MAX * 64];   // ping: pre-scaled features (norm_src * h)
__device__ float g_b[N_MAX * 64];   // pong
__device__ int g_blk_sum[NBLK_SCAN];

// ---------------- threefry-2x32 (exact JAX algorithm, partitionable path) ----------------
__device__ __forceinline__ void d_threefry(uint32_t k0, uint32_t k1,
                                           uint32_t x0, uint32_t x1,
                                           uint32_t& y0, uint32_t& y1) {
    uint32_t k2 = k0 ^ k1 ^ 0x1BD11BDAu;
    x0 += k0; x1 += k1;
#define TFR(r) { x0 += x1; x1 = __funnelshift_l(x1, x1, r); x1 ^= x0; }
    TFR(13) TFR(15) TFR(26) TFR(6)
    x0 += k1; x1 += k2 + 1u;
    TFR(17) TFR(29) TFR(16) TFR(24)
    x0 += k2; x1 += k0 + 2u;
    TFR(13) TFR(15) TFR(26) TFR(6)
    x0 += k0; x1 += k1 + 3u;
    TFR(17) TFR(29) TFR(16) TFR(24)
    x0 += k1; x1 += k2 + 4u;
    TFR(13) TFR(15) TFR(26) TFR(6)
    x0 += k2; x1 += k0 + 5u;
#undef TFR
    y0 = x0; y1 = x1;
}

static inline uint32_t h_rotl(uint32_t x, int r) { return (x << r) | (x >> (32 - r)); }
static void h_threefry(uint32_t k0, uint32_t k1, uint32_t x0, uint32_t x1,
                       uint32_t& y0, uint32_t& y1) {
    uint32_t k2 = k0 ^ k1 ^ 0x1BD11BDAu;
    x0 += k0; x1 += k1;
#define TFR(r) { x0 += x1; x1 = h_rotl(x1, r); x1 ^= x0; }
    TFR(13) TFR(15) TFR(26) TFR(6)
    x0 += k1; x1 += k2 + 1u;
    TFR(17) TFR(29) TFR(16) TFR(24)
    x0 += k2; x1 += k0 + 2u;
    TFR(13) TFR(15) TFR(26) TFR(6)
    x0 += k0; x1 += k1 + 3u;
    TFR(17) TFR(29) TFR(16) TFR(24)
    x0 += k1; x1 += k2 + 4u;
    TFR(13) TFR(15) TFR(26) TFR(6)
    x0 += k2; x1 += k0 + 5u;
#undef TFR
    y0 = x0; y1 = x1;
}

// ---------------- graph prep ----------------
__global__ void k_degree(const int* __restrict__ src, const int* __restrict__ dst, int e) {
    int i = blockIdx.x * blockDim.x + threadIdx.x;
    if (i < e) {
        atomicAdd(&P_DEG_OUT[src[i]], 1);
        atomicAdd(&P_DEG_IN[dst[i]], 1);
    }
}

// fused: norms + single-pass exclusive scan (decoupled lookback) -> row_ptr / fill
// + U0 = norm_src * x  (smem-shared norms, coalesced float4)
__global__ void k_scan_norm_scale(const float* __restrict__ x, int n, int e) {
    __shared__ int s[1024];
    __shared__ float snorm[1024];
    __shared__ int s_prefix;
    int b = blockIdx.x, t = threadIdx.x, i = b * 1024 + t;
    int din = (i < n) ? P_DEG_IN[i] : 0;
    float ns = 0.f;
    if (i < n) {
        int a = P_DEG_OUT[i];
        ns = (a > 0) ? rsqrtf((float)a) : 0.f;
        g_norm_src[i] = ns;
        g_norm_dst[i] = (din > 0) ? rsqrtf((float)din) : 0.f;
    }
    snorm[t] = ns;
    s[t] = din;
    __syncthreads();
    for (int off = 1; off < 1024; off <<= 1) {
        int a = (t >= off) ? s[t - off] : 0;
        __syncthreads();
        s[t] += a;
        __syncthreads();
    }
    if (t == 0) {
        s_prefix = 0;
        g_blk_sum[b] = s[1023];
        __threadfence();
        *((volatile int*)&P_FLAG[b]) = 1;
    }
    __syncthreads();
    if (t < b) {
        while (*((volatile int*)&P_FLAG[t]) == 0) {}
        int v = *((volatile int*)&g_blk_sum[t]);
        atomicAdd(&s_prefix, v);
    }
    __syncthreads();
    int excl = s[t] - din + s_prefix;
    if (i < n) { g_row_ptr[i] = excl; g_fill[i] = excl; }
    if (i == 0) g_row_ptr[n] = e;

    // fused scale: g_a[node][:] = norm_src[node] * x[node][:]
    const float4* x4 = (const float4*)x;
    int f4base = b * 1024 * 16;
#pragma unroll
    for (int q = 0; q < 16; q++) {
        int idx = f4base + q * 1024 + t;
        if (idx < n * 16) {
            float nv = snorm[(idx >> 4) - b * 1024];
            float4 v = x4[idx];
            v.x *= nv; v.y *= nv; v.z *= nv; v.w *= nv;
            ((float4*)g_a)[idx] = v;
        }
    }
}

__global__ void k_csr(const int* __restrict__ src, const int* __restrict__ dst, int e) {
    int i = blockIdx.x * blockDim.x + threadIdx.x;
    if (i < e) {
        int p = atomicAdd(&g_fill[dst[i]], 1);
        g_col[p] = src[i];
    }
}

// ---------------- packed f32x2 helpers ----------------
__device__ __forceinline__ unsigned long long pk2(float x, float y) {
    unsigned long long r;
    asm("mov.b64 %0, {%1,%2};" : "=l"(r) : "f"(x), "f"(y));
    return r;
}
__device__ __forceinline__ void fma2(unsigned long long& d, unsigned long long a, unsigned long long b) {
    asm("fma.rn.f32x2 %0, %1, %2, %0;" : "+l"(d) : "l"(a), "l"(b));
}
__device__ __forceinline__ void add2(unsigned long long& d, unsigned long long v) {
    asm("add.rn.f32x2 %0, %0, %1;" : "+l"(d) : "l"(v));
}
__device__ __forceinline__ float2 upk2(unsigned long long v) {
    float2 r;
    asm("mov.b64 {%0,%1}, %2;" : "=f"(r.x), "=f"(r.y) : "l"(v));
    return r;
}

// ---------------- fused aggregation + tiled GEMM + epilogue ----------------
// Block = 256 threads, 64 nodes.
//  phase 1: warp w gathers nodes base+8w..base+8w+7 into sS[64][66].
//           Feature loads via __ldcg (L2-only: no L1 allocate/fill wavefronts —
//           hit rate ~0 on the 25.6MB random working set). int4 col loads,
//           8-edge unroll, packed FADD2 accumulate, threefry interleaved
//           (proven free here in R10/R11).
//  phase 2: tiled GEMM vs staged W; a-operands loaded as float2 over k-pairs
//           (4 LDS.64 broadcasts per 2k instead of 8 LDS.32 — crossbar -33%).
//  phase 3: epilogue (norm_dst, bias, relu, dropout, norm_src prescale)
template <int LAYER>
__global__ void __launch_bounds__(256) k_aggemm(const float* __restrict__ U,
                                                float* __restrict__ Unext,
                                                const float* __restrict__ W,
                                                const float* __restrict__ bias,
                                                uint32_t key0, uint32_t key1, int n) {
    __shared__ unsigned long long sW[64 * 32]; // [k][cpair] packed (W[k][2c], W[k][2c+1])
    __shared__ float sS[AGG_NPB * SS_STRIDE];  // [local node][k], padded
    int t = threadIdx.x;
    int base = blockIdx.x * AGG_NPB;
    int w = t >> 5, lane = t & 31;
    int rid = t >> 4;       // epilogue row id
    int cid = t & 15;       // epilogue col-pair id

    // stage W (16KB; one-time per 64 nodes)
    const float2* Wv = (const float2*)W;
#pragma unroll
    for (int q = 0; q < 8; q++) {
        int idx = t + q * 256;
        float2 wv = Wv[idx];
        sW[idx] = pk2(wv.x, wv.y);
    }

    // phase 1: gather-sum 8 nodes per warp (lane = col pair); threefry interleaved
    uint32_t keepmask = 0;
    const unsigned long long* T2 = (const unsigned long long*)U;
#pragma unroll 1
    for (int r = 0; r < 8; r++) {
        int node = base + w * 8 + r;
        unsigned long long acc0 = 0ull, acc1 = 0ull;
        int s = 0, e = 0;
        if (node < n) { s = g_row_ptr[node]; e = g_row_ptr[node + 1]; }

        // dropout threefry for epilogue element pair r (hidden under gathers)
        if (LAYER != 2) {
            int en = base + rid + 16 * (r >> 1);
            int ec = cid + 16 * (r & 1);
            uint32_t idx = (uint32_t)en * 64u + 2u * (uint32_t)ec;
            uint32_t y0, y1, z0, z1;
            d_threefry(key0, key1, 0u, idx, y0, y1);
            d_threefry(key0, key1, 0u, idx + 1u, z0, z1);
            keepmask |= (1u ^ ((y0 ^ y1) >> 31)) << (2 * r);
            keepmask |= (1u ^ ((z0 ^ z1) >> 31)) << (2 * r + 1);
        }

        int i = s;
        for (; i < e && (i & 3); i++) {            // align to int4
            add2(acc0, __ldcg(&T2[g_col[i] * 32 + lane]));
        }
        for (; i + 8 <= e; i += 8) {               // 8 edges / iter
            int4 c0 = *(const int4*)&g_col[i];
            int4 c1 = *(const int4*)&g_col[i + 4];
            unsigned long long v0 = __ldcg(&T2[c0.x * 32 + lane]);
            unsigned long long v1 = __ldcg(&T2[c0.y * 32 + lane]);
            unsigned long long v2 = __ldcg(&T2[c0.z * 32 + lane]);
            unsigned long long v3 = __ldcg(&T2[c0.w * 32 + lane]);
            unsigned long long v4 = __ldcg(&T2[c1.x * 32 + lane]);
            unsigned long long v5 = __ldcg(&T2[c1.y * 32 + lane]);
            unsigned long long v6 = __ldcg(&T2[c1.z * 32 + lane]);
            unsigned long long v7 = __ldcg(&T2[c1.w * 32 + lane]);
            add2(acc0, v0); add2(acc1, v1);
            add2(acc0, v2); add2(acc1, v3);
            add2(acc0, v4); add2(acc1, v5);
            add2(acc0, v6); add2(acc1, v7);
        }
        if (i + 4 <= e) {                           // 4 edges
            int4 c0 = *(const int4*)&g_col[i];
            unsigned long long v0 = __ldcg(&T2[c0.x * 32 + lane]);
            unsigned long long v1 = __ldcg(&T2[c0.y * 32 + lane]);
            unsigned long long v2 = __ldcg(&T2[c0.z * 32 + lane]);
            unsigned long long v3 = __ldcg(&T2[c0.w * 32 + lane]);
            add2(acc0, v0); add2(acc1, v1);
            add2(acc0, v2); add2(acc1, v3);
            i += 4;
        }
        for (; i < e; i++) {                        // tail
            add2(acc0, __ldcg(&T2[g_col[i] * 32 + lane]));
        }
        add2(acc0, acc1);
        ((unsigned long long*)&sS[(w * 8 + r) * SS_STRIDE])[lane] = acc0;
    }
    __syncthreads();

    // phase 2: tiled GEMM over k-pairs. thread: rows rid+16i, cpairs cid+16j.
    unsigned long long acc[4][2];
#pragma unroll
    for (int i = 0; i < 4; i++)
#pragma unroll
        for (int j = 0; j < 2; j++) acc[i][j] = 0ull;

#pragma unroll 4
    for (int kk = 0; kk < 32; kk++) {
        float2 a2[4];
        unsigned long long b0[2], b1[2];
#pragma unroll
        for (int i = 0; i < 4; i++)
            a2[i] = *(const float2*)&sS[(rid + 16 * i) * SS_STRIDE + 2 * kk];
#pragma unroll
        for (int j = 0; j < 2; j++) {
            b0[j] = sW[(2 * kk) * 32 + cid + 16 * j];
            b1[j] = sW[(2 * kk + 1) * 32 + cid + 16 * j];
        }
#pragma unroll
        for (int i = 0; i < 4; i++) {
            unsigned long long ax = pk2(a2[i].x, a2[i].x);
            unsigned long long ay = pk2(a2[i].y, a2[i].y);
#pragma unroll
            for (int j = 0; j < 2; j++) {
                fma2(acc[i][j], ax, b0[j]);
                fma2(acc[i][j], ay, b1[j]);
            }
        }
    }

    // phase 3: epilogue (element pair r = 2*i + j  ->  keepmask bits 2r, 2r+1)
#pragma unroll
    for (int i = 0; i < 4; i++) {
        int node = base + rid + 16 * i;
        if (node < n) {
            float nd = g_norm_dst[node];
            float ns = (LAYER != 2) ? g_norm_src[node] : 0.f;
#pragma unroll
            for (int j = 0; j < 2; j++) {
                int c = cid + 16 * j;
                float2 bb = ((const float2*)bias)[c];
                float2 v = upk2(acc[i][j]);
                float ox = v.x * nd + bb.x;
                float oy = v.y * nd + bb.y;
                if (LAYER != 2) {
                    ox = fmaxf(ox, 0.f);
                    oy = fmaxf(oy, 0.f);
                    int r = 2 * i + j;
                    bool keep0 = (keepmask >> (2 * r)) & 1u;
                    bool keep1 = (keepmask >> (2 * r + 1)) & 1u;
                    ox = keep0 ? ox * 2.f * ns : 0.f;
                    oy = keep1 ? oy * 2.f * ns : 0.f;
                }
                ((float2*)Unext)[node * 32 + c] = make_float2(ox, oy);
            }
        }
    }
}

// ---------------- launch ----------------
extern "C" void kernel_launch(void* const* d_in, const int* in_sizes, int n_in,
                              void* d_out, int out_size) {
    const float* x  = (const float*)d_in[0];
    const float* W0 = (const float*)d_in[1];
    const float* b0 = (const float*)d_in[2];
    const float* W1 = (const float*)d_in[3];
    const float* b1 = (const float*)d_in[4];
    const float* W2 = (const float*)d_in[5];
    const float* b2 = (const float*)d_in[6];
    const int*   src = (const int*)d_in[7];
    const int*   dst = (const int*)d_in[8];
    int n = in_sizes[0] / 64;
    int e = in_sizes[7];
    float* out = (float*)d_out;

    int nb = (n + 1023) / 1024;   // <= 98: all scan blocks resident, lookback safe

    uint32_t d0k0, d0k1, d1k0, d1k1;
    h_threefry(0u, 1u, 0u, 0u, d0k0, d0k1);
    h_threefry(0u, 1u, 0u, 1u, d1k0, d1k1);

    float* gA; cudaGetSymbolAddress((void**)&gA, g_a);
    float* gB; cudaGetSymbolAddress((void**)&gB, g_b);
    void* pZ; cudaGetSymbolAddress(&pZ, g_zbuf);

    int aB = (n + AGG_NPB - 1) / AGG_NPB;

    cudaMemsetAsync(pZ, 0, (size_t)(2 * N_MAX + NBLK_SCAN) * sizeof(int));

    k_degree<<<(e + 255) / 256, 256>>>(src, dst, e);             // 0
    k_scan_norm_scale<<<nb, 1024>>>(x, n, e);                    // 1
    k_csr<<<(e + 255) / 256, 256>>>(src, dst, e);                // 2
    k_aggemm<0><<<aB, 256>>>(gA, gB, W0, b0, d0k0, d0k1, n);     // 3 (profiled)
    k_aggemm<1><<<aB, 256>>>(gB, gA, W1, b1, d1k0, d1k1, n);     // 4
    k_aggemm<2><<<aB, 256>>>(gA, out, W2, b2, 0u, 0u, n);        // 5
}

// round 13
// speedup vs baseline: 1.0459x; 1.0005x over previous
#include <cuda_runtime.h>
#include <cstdint>

#define N_MAX 100000
#define E_MAX 1600000
#define NBLK_SCAN 128   // max scan blocks (n/1024 <= 98)
#define GPB 64          // nodes per gemm block
#define SS_STRIDE 66    // padded row stride for sS (floats)

// ---------------- scratch (static device memory; no allocation) ----------------
// single zero-init buffer: [deg_out | deg_in | blk_flag]
__device__ int   g_zbuf[2 * N_MAX + NBLK_SCAN];
#define P_DEG_OUT (g_zbuf)
#define P_DEG_IN  (g_zbuf + N_MAX)
#define P_FLAG    (g_zbuf + 2 * N_MAX)
__device__ float g_norm_src[N_MAX];
__device__ float g_norm_dst[N_MAX];
__device__ int   g_row_ptr[N_MAX + 1];
__device__ int   g_fill[N_MAX];
__device__ int   g_col[E_MAX];
__device__ float g_a[N_MAX * 64];   // ping: pre-scaled features (norm_src * h)
__device__ float g_b[N_MAX * 64];   // pong
__device__ float g_s[N_MAX * 64];   // aggregated sums (gather output)
__device__ int g_blk_sum[NBLK_SCAN];

// ---------------- threefry-2x32 (exact JAX algorithm, partitionable path) ----------------
__device__ __forceinline__ void d_threefry(uint32_t k0, uint32_t k1,
                                           uint32_t x0, uint32_t x1,
                                           uint32_t& y0, uint32_t& y1) {
    uint32_t k2 = k0 ^ k1 ^ 0x1BD11BDAu;
    x0 += k0; x1 += k1;
#define TFR(r) { x0 += x1; x1 = __funnelshift_l(x1, x1, r); x1 ^= x0; }
    TFR(13) TFR(15) TFR(26) TFR(6)
    x0 += k1; x1 += k2 + 1u;
    TFR(17) TFR(29) TFR(16) TFR(24)
    x0 += k2; x1 += k0 + 2u;
    TFR(13) TFR(15) TFR(26) TFR(6)
    x0 += k0; x1 += k1 + 3u;
    TFR(17) TFR(29) TFR(16) TFR(24)
    x0 += k1; x1 += k2 + 4u;
    TFR(13) TFR(15) TFR(26) TFR(6)
    x0 += k2; x1 += k0 + 5u;
#undef TFR
    y0 = x0; y1 = x1;
}

static inline uint32_t h_rotl(uint32_t x, int r) { return (x << r) | (x >> (32 - r)); }
static void h_threefry(uint32_t k0, uint32_t k1, uint32_t x0, uint32_t x1,
                       uint32_t& y0, uint32_t& y1) {
    uint32_t k2 = k0 ^ k1 ^ 0x1BD11BDAu;
    x0 += k0; x1 += k1;
#define TFR(r) { x0 += x1; x1 = h_rotl(x1, r); x1 ^= x0; }
    TFR(13) TFR(15) TFR(26) TFR(6)
    x0 += k1; x1 += k2 + 1u;
    TFR(17) TFR(29) TFR(16) TFR(24)
    x0 += k2; x1 += k0 + 2u;
    TFR(13) TFR(15) TFR(26) TFR(6)
    x0 += k0; x1 += k1 + 3u;
    TFR(17) TFR(29) TFR(16) TFR(24)
    x0 += k1; x1 += k2 + 4u;
    TFR(13) TFR(15) TFR(26) TFR(6)
    x0 += k2; x1 += k0 + 5u;
#undef TFR
    y0 = x0; y1 = x1;
}

// ---------------- graph prep ----------------
__global__ void k_degree(const int* __restrict__ src, const int* __restrict__ dst, int e) {
    int i = blockIdx.x * blockDim.x + threadIdx.x;
    if (i < e) {
        atomicAdd(&P_DEG_OUT[src[i]], 1);
        atomicAdd(&P_DEG_IN[dst[i]], 1);
    }
}

// fused: norms + single-pass exclusive scan (decoupled lookback) -> row_ptr / fill
// + U0 = norm_src * x  (smem-shared norms, coalesced float4)
__global__ void k_scan_norm_scale(const float* __restrict__ x, int n, int e) {
    __shared__ int s[1024];
    __shared__ float snorm[1024];
    __shared__ int s_prefix;
    int b = blockIdx.x, t = threadIdx.x, i = b * 1024 + t;
    int din = (i < n) ? P_DEG_IN[i] : 0;
    float ns = 0.f;
    if (i < n) {
        int a = P_DEG_OUT[i];
        ns = (a > 0) ? rsqrtf((float)a) : 0.f;
        g_norm_src[i] = ns;
        g_norm_dst[i] = (din > 0) ? rsqrtf((float)din) : 0.f;
    }
    snorm[t] = ns;
    s[t] = din;
    __syncthreads();
    for (int off = 1; off < 1024; off <<= 1) {
        int a = (t >= off) ? s[t - off] : 0;
        __syncthreads();
        s[t] += a;
        __syncthreads();
    }
    if (t == 0) {
        s_prefix = 0;
        g_blk_sum[b] = s[1023];
        __threadfence();
        *((volatile int*)&P_FLAG[b]) = 1;
    }
    __syncthreads();
    if (t < b) {
        while (*((volatile int*)&P_FLAG[t]) == 0) {}
        int v = *((volatile int*)&g_blk_sum[t]);
        atomicAdd(&s_prefix, v);
    }
    __syncthreads();
    int excl = s[t] - din + s_prefix;
    if (i < n) { g_row_ptr[i] = excl; g_fill[i] = excl; }
    if (i == 0) g_row_ptr[n] = e;

    // fused scale: g_a[node][:] = norm_src[node] * x[node][:]
    const float4* x4 = (const float4*)x;
    int f4base = b * 1024 * 16;
#pragma unroll
    for (int q = 0; q < 16; q++) {
        int idx = f4base + q * 1024 + t;
        if (idx < n * 16) {
            float nv = snorm[(idx >> 4) - b * 1024];
            float4 v = x4[idx];
            v.x *= nv; v.y *= nv; v.z *= nv; v.w *= nv;
            ((float4*)g_a)[idx] = v;
        }
    }
}

__global__ void k_csr(const int* __restrict__ src, const int* __restrict__ dst, int e) {
    int i = blockIdx.x * blockDim.x + threadIdx.x;
    if (i < e) {
        int p = atomicAdd(&g_fill[dst[i]], 1);
        g_col[p] = src[i];
    }
}

// ---------------- packed f32x2 helpers ----------------
__device__ __forceinline__ unsigned long long pk2(float x, float y) {
    unsigned long long r;
    asm("mov.b64 %0, {%1,%2};" : "=l"(r) : "f"(x), "f"(y));
    return r;
}
__device__ __forceinline__ void fma2(unsigned long long& d, unsigned long long a, unsigned long long b) {
    asm("fma.rn.f32x2 %0, %1, %2, %0;" : "+l"(d) : "l"(a), "l"(b));
}
__device__ __forceinline__ void add2(unsigned long long& d, unsigned long long v) {
    asm("add.rn.f32x2 %0, %0, %1;" : "+l"(d) : "l"(v));
}
__device__ __forceinline__ float2 upk2(unsigned long long v) {
    float2 r;
    asm("mov.b64 {%0,%1}, %2;" : "=f"(r.x), "=f"(r.y) : "l"(v));
    return r;
}

// ---------------- pure gather: S[v] = sum_{u in N(v)} U[u] ----------------
// one warp per node; lane = col pair. No barriers, no phases — warps run free.
__global__ void __launch_bounds__(256) k_agg(const float* __restrict__ U, int n) {
    int gw = (blockIdx.x * blockDim.x + threadIdx.x) >> 5;
    int lane = threadIdx.x & 31;
    if (gw >= n) return;
    int s = g_row_ptr[gw], e = g_row_ptr[gw + 1];
    const unsigned long long* T2 = (const unsigned long long*)U;
    unsigned long long acc0 = 0ull, acc1 = 0ull;

    int i = s;
    for (; i < e && (i & 3); i++)              // align to int4
        add2(acc0, T2[g_col[i] * 32 + lane]);
    for (; i + 8 <= e; i += 8) {               // 8 edges / iter
        int4 c0 = *(const int4*)&g_col[i];
        int4 c1 = *(const int4*)&g_col[i + 4];
        unsigned long long v0 = T2[c0.x * 32 + lane];
        unsigned long long v1 = T2[c0.y * 32 + lane];
        unsigned long long v2 = T2[c0.z * 32 + lane];
        unsigned long long v3 = T2[c0.w * 32 + lane];
        unsigned long long v4 = T2[c1.x * 32 + lane];
        unsigned long long v5 = T2[c1.y * 32 + lane];
        unsigned long long v6 = T2[c1.z * 32 + lane];
        unsigned long long v7 = T2[c1.w * 32 + lane];
        add2(acc0, v0); add2(acc1, v1);
        add2(acc0, v2); add2(acc1, v3);
        add2(acc0, v4); add2(acc1, v5);
        add2(acc0, v6); add2(acc1, v7);
    }
    if (i + 4 <= e) {
        int4 c0 = *(const int4*)&g_col[i];
        unsigned long long v0 = T2[c0.x * 32 + lane];
        unsigned long long v1 = T2[c0.y * 32 + lane];
        unsigned long long v2 = T2[c0.z * 32 + lane];
        unsigned long long v3 = T2[c0.w * 32 + lane];
        add2(acc0, v0); add2(acc1, v1);
        add2(acc0, v2); add2(acc1, v3);
        i += 4;
    }
    for (; i < e; i++)
        add2(acc0, T2[g_col[i] * 32 + lane]);
    add2(acc0, acc1);
    ((unsigned long long*)g_s)[gw * 32 + lane] = acc0;
}

// ---------------- GEMM + epilogue: out = epi(norm_dst*(S@W)+b) ----------------
// 256 threads, 64 nodes/block. Stage S tile coalesced + W packed; threefry
// computed between stage-load issue and STS (overlaps load latency).
// Thread register tile: rows rid+16i (i<4), col-pairs cid+16j (j<2).
template <int LAYER>
__global__ void __launch_bounds__(256) k_gemm_epi(float* __restrict__ Unext,
                                                  const float* __restrict__ W,
                                                  const float* __restrict__ bias,
                                                  uint32_t key0, uint32_t key1, int n) {
    __shared__ unsigned long long sW[64 * 32]; // [k][cpair] packed
    __shared__ float sS[GPB * SS_STRIDE];      // [local node][k], padded
    int t = threadIdx.x;
    int base = blockIdx.x * GPB;
    int rid = t >> 4;
    int cid = t & 15;

    // issue W stage
    const float2* Wv = (const float2*)W;
    float2 wreg[8];
#pragma unroll
    for (int q = 0; q < 8; q++) wreg[q] = Wv[t + q * 256];

    // issue S-tile stage loads (64 rows x 64 floats; 4 float4 per thread)
    const float4* S4 = (const float4*)g_s;
    float4 sreg[4];
#pragma unroll
    for (int q = 0; q < 4; q++) {
        int li = q * 256 + t;          // 0..1023 (local float4 index)
        int row = li >> 4;
        int node = base + row;
        sreg[q] = (node < n) ? S4[node * 16 + (li & 15)]
                             : make_float4(0.f, 0.f, 0.f, 0.f);
    }

    // threefry (ALU) while stage loads are in flight
    uint32_t keepmask = 0;
    if (LAYER != 2) {
#pragma unroll
        for (int r = 0; r < 8; r++) {
            int node = base + rid + 16 * (r >> 1);
            int c = cid + 16 * (r & 1);
            uint32_t idx = (uint32_t)node * 64u + 2u * (uint32_t)c;
            uint32_t y0, y1, z0, z1;
            d_threefry(key0, key1, 0u, idx, y0, y1);
            d_threefry(key0, key1, 0u, idx + 1u, z0, z1);
            keepmask |= (1u ^ ((y0 ^ y1) >> 31)) << (2 * r);
            keepmask |= (1u ^ ((z0 ^ z1) >> 31)) << (2 * r + 1);
        }
    }

    // commit stages to smem
#pragma unroll
    for (int q = 0; q < 8; q++) sW[t + q * 256] = pk2(wreg[q].x, wreg[q].y);
#pragma unroll
    for (int q = 0; q < 4; q++) {
        int li = q * 256 + t;
        int row = li >> 4;
        float* p = &sS[row * SS_STRIDE + (li & 15) * 4];
        p[0] = sreg[q].x; p[1] = sreg[q].y; p[2] = sreg[q].z; p[3] = sreg[q].w;
    }
    __syncthreads();

    // GEMM: 4 rows x 2 col-pairs per thread
    unsigned long long acc[4][2];
#pragma unroll
    for (int i = 0; i < 4; i++)
#pragma unroll
        for (int j = 0; j < 2; j++) acc[i][j] = 0ull;

#pragma unroll 8
    for (int k = 0; k < 64; k++) {
        unsigned long long a[4], b[2];
#pragma unroll
        for (int i = 0; i < 4; i++) {
            float h = sS[(rid + 16 * i) * SS_STRIDE + k];
            a[i] = pk2(h, h);
        }
#pragma unroll
        for (int j = 0; j < 2; j++) b[j] = sW[k * 32 + cid + 16 * j];
#pragma unroll
        for (int i = 0; i < 4; i++)
#pragma unroll
            for (int j = 0; j < 2; j++) fma2(acc[i][j], a[i], b[j]);
    }

    // epilogue (element pair r = 2*i + j -> keepmask bits 2r, 2r+1)
#pragma unroll
    for (int i = 0; i < 4; i++) {
        int node = base + rid + 16 * i;
        if (node < n) {
            float nd = g_norm_dst[node];
            float ns = (LAYER != 2) ? g_norm_src[node] : 0.f;
#pragma unroll
            for (int j = 0; j < 2; j++) {
                int c = cid + 16 * j;
                float2 bb = ((const float2*)bias)[c];
                float2 v = upk2(acc[i][j]);
                float ox = v.x * nd + bb.x;
                float oy = v.y * nd + bb.y;
                if (LAYER != 2) {
                    ox = fmaxf(ox, 0.f);
                    oy = fmaxf(oy, 0.f);
                    int r = 2 * i + j;
                    bool keep0 = (keepmask >> (2 * r)) & 1u;
                    bool keep1 = (keepmask >> (2 * r + 1)) & 1u;
                    ox = keep0 ? ox * 2.f * ns : 0.f;
                    oy = keep1 ? oy * 2.f * ns : 0.f;
                }
                ((float2*)Unext)[node * 32 + c] = make_float2(ox, oy);
            }
        }
    }
}

// ---------------- launch ----------------
extern "C" void kernel_launch(void* const* d_in, const int* in_sizes, int n_in,
                              void* d_out, int out_size) {
    const float* x  = (const float*)d_in[0];
    const float* W0 = (const float*)d_in[1];
    const float* b0 = (const float*)d_in[2];
    const float* W1 = (const float*)d_in[3];
    const float* b1 = (const float*)d_in[4];
    const float* W2 = (const float*)d_in[5];
    const float* b2 = (const float*)d_in[6];
    const int*   src = (const int*)d_in[7];
    const int*   dst = (const int*)d_in[8];
    int n = in_sizes[0] / 64;
    int e = in_sizes[7];
    float* out = (float*)d_out;

    int nb = (n + 1023) / 1024;   // <= 98: all scan blocks resident, lookback safe

    uint32_t d0k0, d0k1, d1k0, d1k1;
    h_threefry(0u, 1u, 0u, 0u, d0k0, d0k1);
    h_threefry(0u, 1u, 0u, 1u, d1k0, d1k1);

    float* gA; cudaGetSymbolAddress((void**)&gA, g_a);
    float* gB; cudaGetSymbolAddress((void**)&gB, g_b);
    void* pZ; cudaGetSymbolAddress(&pZ, g_zbuf);

    int aB = (n * 32 + 255) / 256;        // warp per node
    int gBk = (n + GPB - 1) / GPB;        // 64 nodes per gemm block

    cudaMemsetAsync(pZ, 0, (size_t)(2 * N_MAX + NBLK_SCAN) * sizeof(int));

    k_degree<<<(e + 255) / 256, 256>>>(src, dst, e);                  // 0
    k_scan_norm_scale<<<nb, 1024>>>(x, n, e);                         // 1
    k_csr<<<(e + 255) / 256, 256>>>(src, dst, e);                     // 2
    k_agg<<<aB, 256>>>(gA, n);                                        // 3 (profiled)
    k_gemm_epi<0><<<gBk, 256>>>(gB, W0, b0, d0k0, d0k1, n);           // 4
    k_agg<<<aB, 256>>>(gB, n);                                        // 5
    k_gemm_epi<1><<<gBk, 256>>>(gA, W1, b1, d1k0, d1k1, n);           // 6
    k_agg<<<aB, 256>>>(gA, n);                                        // 7
    k_gemm_epi<2><<<gBk, 256>>>(out, W2, b2, 0u, 0u, n);              // 8
}

// round 14
// speedup vs baseline: 1.0915x; 1.0436x over previous
#include <cuda_runtime.h>
#include <cuda_fp16.h>
#include <cstdint>

#define N_MAX 100000
#define E_MAX 1600000
#define NBLK_SCAN 128   // max scan blocks (n/1024 <= 98)
#define GPB 64          // nodes per gemm block
#define SS_STRIDE 66    // padded row stride for sS (floats)

// ---------------- scratch (static device memory; no allocation) ----------------
__device__ int   g_zbuf[2 * N_MAX + NBLK_SCAN];   // [deg_out | deg_in | blk_flag]
#define P_DEG_OUT (g_zbuf)
#define P_DEG_IN  (g_zbuf + N_MAX)
#define P_FLAG    (g_zbuf + 2 * N_MAX)
__device__ float g_norm_src[N_MAX];
__device__ float g_norm_dst[N_MAX];
__device__ int   g_row_ptr[N_MAX + 1];
__device__ int   g_fill[N_MAX];
__device__ int   g_col[E_MAX];
__device__ __half g_a[N_MAX * 64];  // ping: pre-scaled features (fp16)
__device__ __half g_b[N_MAX * 64];  // pong
__device__ float g_s[N_MAX * 64];   // aggregated sums (fp32)
__device__ unsigned char g_mask[2 * N_MAX * 32];  // per layer: byte per col-pair
__device__ int g_blk_sum[NBLK_SCAN];

// ---------------- threefry-2x32 (exact JAX algorithm, partitionable path) ----------------
__device__ __forceinline__ void d_threefry(uint32_t k0, uint32_t k1,
                                           uint32_t x0, uint32_t x1,
                                           uint32_t& y0, uint32_t& y1) {
    uint32_t k2 = k0 ^ k1 ^ 0x1BD11BDAu;
    x0 += k0; x1 += k1;
#define TFR(r) { x0 += x1; x1 = __funnelshift_l(x1, x1, r); x1 ^= x0; }
    TFR(13) TFR(15) TFR(26) TFR(6)
    x0 += k1; x1 += k2 + 1u;
    TFR(17) TFR(29) TFR(16) TFR(24)
    x0 += k2; x1 += k0 + 2u;
    TFR(13) TFR(15) TFR(26) TFR(6)
    x0 += k0; x1 += k1 + 3u;
    TFR(17) TFR(29) TFR(16) TFR(24)
    x0 += k1; x1 += k2 + 4u;
    TFR(13) TFR(15) TFR(26) TFR(6)
    x0 += k2; x1 += k0 + 5u;
#undef TFR
    y0 = x0; y1 = x1;
}

static inline uint32_t h_rotl(uint32_t x, int r) { return (x << r) | (x >> (32 - r)); }
static void h_threefry(uint32_t k0, uint32_t k1, uint32_t x0, uint32_t x1,
                       uint32_t& y0, uint32_t& y1) {
    uint32_t k2 = k0 ^ k1 ^ 0x1BD11BDAu;
    x0 += k0; x1 += k1;
#define TFR(r) { x0 += x1; x1 = h_rotl(x1, r); x1 ^= x0; }
    TFR(13) TFR(15) TFR(26) TFR(6)
    x0 += k1; x1 += k2 + 1u;
    TFR(17) TFR(29) TFR(16) TFR(24)
    x0 += k2; x1 += k0 + 2u;
    TFR(13) TFR(15) TFR(26) TFR(6)
    x0 += k0; x1 += k1 + 3u;
    TFR(17) TFR(29) TFR(16) TFR(24)
    x0 += k1; x1 += k2 + 4u;
    TFR(13) TFR(15) TFR(26) TFR(6)
    x0 += k2; x1 += k0 + 5u;
#undef TFR
    y0 = x0; y1 = x1;
}

// ---------------- degree count + dropout-mask precompute ----------------
// Edge part is L2-atomic-latency-bound (issue ~5%); the threefry ALU work fills
// idle issue slots (R11: +11us for BOTH layers vs +21us/layer if exposed).
__global__ void k_degree_mask(const int* __restrict__ src, const int* __restrict__ dst,
                              int e, int pairs, int maskWords,
                              uint32_t d0k0, uint32_t d0k1,
                              uint32_t d1k0, uint32_t d1k1) {
    int j = blockIdx.x * blockDim.x + threadIdx.x;
    if (j < e) {
        atomicAdd(&P_DEG_OUT[src[j]], 1);
        atomicAdd(&P_DEG_IN[dst[j]], 1);
    }
    if (j < maskWords) {
        int p0 = 4 * j;                       // first of 4 pair-slots (pairs%4==0)
        int layer = (p0 >= pairs);
        uint32_t k0 = layer ? d1k0 : d0k0;
        uint32_t k1 = layer ? d1k1 : d0k1;
        uint32_t plbase = (uint32_t)(p0 - layer * pairs);
        uint32_t word = 0;
#pragma unroll
        for (int q = 0; q < 4; q++) {
            uint32_t idx = 2u * (plbase + q);  // element index = node*64 + 2c
            uint32_t y0, y1, z0, z1;
            d_threefry(k0, k1, 0u, idx, y0, y1);
            d_threefry(k0, k1, 0u, idx + 1u, z0, z1);
            uint32_t b = (1u ^ ((y0 ^ y1) >> 31)) | ((1u ^ ((z0 ^ z1) >> 31)) << 1);
            word |= b << (8 * q);
        }
        ((uint32_t*)g_mask)[j] = word;
    }
}

// fused: norms + single-pass exclusive scan (decoupled lookback) -> row_ptr / fill
// + U0 = fp16(norm_src * x)
__global__ void k_scan_norm_scale(const float* __restrict__ x, int n, int e) {
    __shared__ int s[1024];
    __shared__ float snorm[1024];
    __shared__ int s_prefix;
    int b = blockIdx.x, t = threadIdx.x, i = b * 1024 + t;
    int din = (i < n) ? P_DEG_IN[i] : 0;
    float ns = 0.f;
    if (i < n) {
        int a = P_DEG_OUT[i];
        ns = (a > 0) ? rsqrtf((float)a) : 0.f;
        g_norm_src[i] = ns;
        g_norm_dst[i] = (din > 0) ? rsqrtf((float)din) : 0.f;
    }
    snorm[t] = ns;
    s[t] = din;
    __syncthreads();
    for (int off = 1; off < 1024; off <<= 1) {
        int a = (t >= off) ? s[t - off] : 0;
        __syncthreads();
        s[t] += a;
        __syncthreads();
    }
    if (t == 0) {
        s_prefix = 0;
        g_blk_sum[b] = s[1023];
        __threadfence();
        *((volatile int*)&P_FLAG[b]) = 1;
    }
    __syncthreads();
    if (t < b) {
        while (*((volatile int*)&P_FLAG[t]) == 0) {}
        int v = *((volatile int*)&g_blk_sum[t]);
        atomicAdd(&s_prefix, v);
    }
    __syncthreads();
    int excl = s[t] - din + s_prefix;
    if (i < n) { g_row_ptr[i] = excl; g_fill[i] = excl; }
    if (i == 0) g_row_ptr[n] = e;

    // fused scale: g_a[node][:] = fp16(norm_src[node] * x[node][:])
    const float4* x4 = (const float4*)x;
    int f4base = b * 1024 * 16;
#pragma unroll
    for (int q = 0; q < 16; q++) {
        int idx = f4base + q * 1024 + t;
        if (idx < n * 16) {
            float nv = snorm[(idx >> 4) - b * 1024];
            float4 v = x4[idx];
            __half2 h0 = __floats2half2_rn(v.x * nv, v.y * nv);
            __half2 h1 = __floats2half2_rn(v.z * nv, v.w * nv);
            uint2 pk;
            pk.x = *reinterpret_cast<uint32_t*>(&h0);
            pk.y = *reinterpret_cast<uint32_t*>(&h1);
            ((uint2*)g_a)[idx] = pk;
        }
    }
}

__global__ void k_csr(const int* __restrict__ src, const int* __restrict__ dst, int e) {
    int i = blockIdx.x * blockDim.x + threadIdx.x;
    if (i < e) {
        int p = atomicAdd(&g_fill[dst[i]], 1);
        g_col[p] = src[i];
    }
}

// ---------------- packed f32x2 helpers ----------------
__device__ __forceinline__ unsigned long long pk2(float x, float y) {
    unsigned long long r;
    asm("mov.b64 %0, {%1,%2};" : "=l"(r) : "f"(x), "f"(y));
    return r;
}
__device__ __forceinline__ void fma2(unsigned long long& d, unsigned long long a, unsigned long long b) {
    asm("fma.rn.f32x2 %0, %1, %2, %0;" : "+l"(d) : "l"(a), "l"(b));
}
__device__ __forceinline__ float2 upk2(unsigned long long v) {
    float2 r;
    asm("mov.b64 {%0,%1}, %2;" : "=f"(r.x), "=f"(r.y) : "l"(v));
    return r;
}

// accumulate one half2 feature load into two fp32 accumulators
__device__ __forceinline__ void acch(float& ax, float& ay, uint32_t h) {
    __half2 h2 = *reinterpret_cast<__half2*>(&h);
    float2 f = __half22float2(h2);
    ax += f.x; ay += f.y;
}

// ---------------- pure gather: S[v] = sum_{u in N(v)} U[u] (fp16 -> fp32) ------
// one warp per node; lane = col pair (half2 = 4B -> warp 128B/edge, 1 wavefront).
__global__ void __launch_bounds__(256) k_agg(const __half* __restrict__ U, int n) {
    int gw = (blockIdx.x * blockDim.x + threadIdx.x) >> 5;
    int lane = threadIdx.x & 31;
    if (gw >= n) return;
    int s = g_row_ptr[gw], e = g_row_ptr[gw + 1];
    const uint32_t* T2 = (const uint32_t*)U;
    float ax0 = 0.f, ay0 = 0.f, ax1 = 0.f, ay1 = 0.f;

    int i = s;
    for (; i < e && (i & 3); i++)              // align to int4
        acch(ax0, ay0, T2[g_col[i] * 32 + lane]);
    for (; i + 8 <= e; i += 8) {               // 8 edges / iter
        int4 c0 = *(const int4*)&g_col[i];
        int4 c1 = *(const int4*)&g_col[i + 4];
        uint32_t v0 = T2[c0.x * 32 + lane];
        uint32_t v1 = T2[c0.y * 32 + lane];
        uint32_t v2 = T2[c0.z * 32 + lane];
        uint32_t v3 = T2[c0.w * 32 + lane];
        uint32_t v4 = T2[c1.x * 32 + lane];
        uint32_t v5 = T2[c1.y * 32 + lane];
        uint32_t v6 = T2[c1.z * 32 + lane];
        uint32_t v7 = T2[c1.w * 32 + lane];
        acch(ax0, ay0, v0); acch(ax1, ay1, v1);
        acch(ax0, ay0, v2); acch(ax1, ay1, v3);
        acch(ax0, ay0, v4); acch(ax1, ay1, v5);
        acch(ax0, ay0, v6); acch(ax1, ay1, v7);
    }
    if (i + 4 <= e) {
        int4 c0 = *(const int4*)&g_col[i];
        uint32_t v0 = T2[c0.x * 32 + lane];
        uint32_t v1 = T2[c0.y * 32 + lane];
        uint32_t v2 = T2[c0.z * 32 + lane];
        uint32_t v3 = T2[c0.w * 32 + lane];
        acch(ax0, ay0, v0); acch(ax1, ay1, v1);
        acch(ax0, ay0, v2); acch(ax1, ay1, v3);
        i += 4;
    }
    for (; i < e; i++)
        acch(ax0, ay0, T2[g_col[i] * 32 + lane]);
    ((float2*)g_s)[gw * 32 + lane] = make_float2(ax0 + ax1, ay0 + ay1);
}

// ---------------- GEMM + epilogue: out = epi(norm_dst*(S@W)+b) ----------------
// 256 threads, 64 nodes/block; thread tile rows rid+16i (i<4), cpairs cid+16j (j<2).
// Dropout mask precomputed in k_degree_mask (byte per (node, cpair)).
template <int LAYER>
__global__ void __launch_bounds__(256) k_gemm_epi(void* __restrict__ Unext,
                                                  const float* __restrict__ W,
                                                  const float* __restrict__ bias,
                                                  int pairs, int n) {
    __shared__ unsigned long long sW[64 * 32]; // [k][cpair] packed
    __shared__ float sS[GPB * SS_STRIDE];      // [local node][k], padded
    int t = threadIdx.x;
    int base = blockIdx.x * GPB;
    int rid = t >> 4;
    int cid = t & 15;

    // issue W stage
    const float2* Wv = (const float2*)W;
    float2 wreg[8];
#pragma unroll
    for (int q = 0; q < 8; q++) wreg[q] = Wv[t + q * 256];

    // issue S-tile stage loads (64 rows x 64 floats; 4 float4 per thread)
    const float4* S4 = (const float4*)g_s;
    float4 sreg[4];
#pragma unroll
    for (int q = 0; q < 4; q++) {
        int li = q * 256 + t;
        int row = li >> 4;
        int node = base + row;
        sreg[q] = (node < n) ? S4[node * 16 + (li & 15)]
                             : make_float4(0.f, 0.f, 0.f, 0.f);
    }

    // mask bytes (L1/L2 cached; block span is 2KB contiguous)
    unsigned char mb[4][2];
    if (LAYER != 2) {
        const unsigned char* mbase = g_mask + LAYER * pairs;
#pragma unroll
        for (int i = 0; i < 4; i++)
#pragma unroll
            for (int j = 0; j < 2; j++)
                mb[i][j] = mbase[(base + rid + 16 * i) * 32 + cid + 16 * j];
    }

    // commit stages to smem
#pragma unroll
    for (int q = 0; q < 8; q++) sW[t + q * 256] = pk2(wreg[q].x, wreg[q].y);
#pragma unroll
    for (int q = 0; q < 4; q++) {
        int li = q * 256 + t;
        int row = li >> 4;
        float* p = &sS[row * SS_STRIDE + (li & 15) * 4];
        p[0] = sreg[q].x; p[1] = sreg[q].y; p[2] = sreg[q].z; p[3] = sreg[q].w;
    }
    __syncthreads();

    // GEMM: 4 rows x 2 col-pairs per thread
    unsigned long long acc[4][2];
#pragma unroll
    for (int i = 0; i < 4; i++)
#pragma unroll
        for (int j = 0; j < 2; j++) acc[i][j] = 0ull;

#pragma unroll 8
    for (int k = 0; k < 64; k++) {
        unsigned long long a[4], b[2];
#pragma unroll
        for (int i = 0; i < 4; i++) {
            float h = sS[(rid + 16 * i) * SS_STRIDE + k];
            a[i] = pk2(h, h);
        }
#pragma unroll
        for (int j = 0; j < 2; j++) b[j] = sW[k * 32 + cid + 16 * j];
#pragma unroll
        for (int i = 0; i < 4; i++)
#pragma unroll
            for (int j = 0; j < 2; j++) fma2(acc[i][j], a[i], b[j]);
    }

    // epilogue
#pragma unroll
    for (int i = 0; i < 4; i++) {
        int node = base + rid + 16 * i;
        if (node < n) {
            float nd = g_norm_dst[node];
            float ns = (LAYER != 2) ? g_norm_src[node] : 0.f;
#pragma unroll
            for (int j = 0; j < 2; j++) {
                int c = cid + 16 * j;
                float2 bb = ((const float2*)bias)[c];
                float2 v = upk2(acc[i][j]);
                float ox = v.x * nd + bb.x;
                float oy = v.y * nd + bb.y;
                if (LAYER != 2) {
                    ox = fmaxf(ox, 0.f);
                    oy = fmaxf(oy, 0.f);
                    ox = (mb[i][j] & 1) ? ox * 2.f * ns : 0.f;
                    oy = (mb[i][j] & 2) ? oy * 2.f * ns : 0.f;
                    ((__half2*)Unext)[node * 32 + c] = __floats2half2_rn(ox, oy);
                } else {
                    ((float2*)Unext)[node * 32 + c] = make_float2(ox, oy);
                }
            }
        }
    }
}

// ---------------- launch ----------------
extern "C" void kernel_launch(void* const* d_in, const int* in_sizes, int n_in,
                              void* d_out, int out_size) {
    const float* x  = (const float*)d_in[0];
    const float* W0 = (const float*)d_in[1];
    const float* b0 = (const float*)d_in[2];
    const float* W1 = (const float*)d_in[3];
    const float* b1 = (const float*)d_in[4];
    const float* W2 = (const float*)d_in[5];
    const float* b2 = (const float*)d_in[6];
    const int*   src = (const int*)d_in[7];
    const int*   dst = (const int*)d_in[8];
    int n = in_sizes[0] / 64;
    int e = in_sizes[7];
    float* out = (float*)d_out;

    int nb = (n + 1023) / 1024;   // <= 98: all scan blocks resident, lookback safe
    int pairs = n * 32;
    int maskWords = (2 * pairs) / 4;

    uint32_t d0k0, d0k1, d1k0, d1k1;
    h_threefry(0u, 1u, 0u, 0u, d0k0, d0k1);
    h_threefry(0u, 1u, 0u, 1u, d1k0, d1k1);

    __half* gA; cudaGetSymbolAddress((void**)&gA, g_a);
    __half* gB; cudaGetSymbolAddress((void**)&gB, g_b);
    void* pZ; cudaGetSymbolAddress(&pZ, g_zbuf);

    int aB = (n * 32 + 255) / 256;        // warp per node
    int gBk = (n + GPB - 1) / GPB;        // 64 nodes per gemm block
    int dThreads = (e > maskWords) ? e : maskWords;

    cudaMemsetAsync(pZ, 0, (size_t)(2 * N_MAX + NBLK_SCAN) * sizeof(int));

    k_degree_mask<<<(dThreads + 255) / 256, 256>>>(src, dst, e, pairs, maskWords,
                                                   d0k0, d0k1, d1k0, d1k1);    // 0
    k_scan_norm_scale<<<nb, 1024>>>(x, n, e);                                  // 1
    k_csr<<<(e + 255) / 256, 256>>>(src, dst, e);                              // 2
    k_agg<<<aB, 256>>>(gA, n);                                                 // 3 (profiled)
    k_gemm_epi<0><<<gBk, 256>>>(gB, W0, b0, pairs, n);                         // 4
    k_agg<<<aB, 256>>>(gB, n);                                                 // 5
    k_gemm_epi<1><<<gBk, 256>>>(gA, W1, b1, pairs, n);                         // 6
    k_agg<<<aB, 256>>>(gA, n);                                                 // 7
    k_gemm_epi<2><<<gBk, 256>>>(out, W2, b2, pairs, n);                        // 8
}